// round 3
// baseline (speedup 1.0000x reference)
#include <cuda_runtime.h>
#include <cuda_bf16.h>
#include <cstdint>

// Problem sizes (reference: N=100000, E=1600000, C=128)
#define MAXN 100000
#define C 128

// Scratch (device globals — allocation-free per harness rules)
__device__ float g_xs[(size_t)MAXN * C];
__device__ float g_agg[(size_t)MAXN * C];
__device__ float g_deg[MAXN];

// ---------------------------------------------------------------------------
// K1: zero agg (float4) and deg
// ---------------------------------------------------------------------------
__global__ void zero_kernel(int n) {
    int idx = blockIdx.x * blockDim.x + threadIdx.x;   // over n*32 (float4 units)
    if (idx < n * 32) {
        float4 z = make_float4(0.f, 0.f, 0.f, 0.f);
        *reinterpret_cast<float4*>(&g_agg[(size_t)idx * 4]) = z;
    }
    if (idx < n) g_deg[idx] = 0.f;
}

// ---------------------------------------------------------------------------
// K2: degree histogram over rows (out-edges of edge_index[0])
// edge_index is INT32 (JAX silently downcasts int64 -> int32 w/o x64 mode)
// ---------------------------------------------------------------------------
__global__ void deg_kernel(const int* __restrict__ ei, int E) {
    int e = blockIdx.x * blockDim.x + threadIdx.x;
    if (e >= E) return;
    int row = ei[e];
    atomicAdd(&g_deg[row], 1.0f);
}

// ---------------------------------------------------------------------------
// K3: xs = x * rsqrt(deg+1)
// ---------------------------------------------------------------------------
__global__ void xs_kernel(const float* __restrict__ x, int n) {
    int idx = blockIdx.x * blockDim.x + threadIdx.x;   // over n*32 float4 units
    if (idx >= n * 32) return;
    int row = idx >> 5;
    float inv = rsqrtf(g_deg[row] + 1.0f);
    float4 v = *reinterpret_cast<const float4*>(&x[(size_t)idx * 4]);
    v.x *= inv; v.y *= inv; v.z *= inv; v.w *= inv;
    *reinterpret_cast<float4*>(&g_xs[(size_t)idx * 4]) = v;
}

// ---------------------------------------------------------------------------
// K4: edge scatter: agg[row] += xs[col].  One warp per edge (grid-stride over
// edges); each lane moves one float4 and issues a single
// red.global.add.v4.f32 (no-return REDG path).
// ---------------------------------------------------------------------------
__global__ void __launch_bounds__(256) scatter_kernel(
        const int* __restrict__ ei, int E) {
    int lane = threadIdx.x & 31;
    int warp_global = (blockIdx.x * blockDim.x + threadIdx.x) >> 5;
    int nwarps = (gridDim.x * blockDim.x) >> 5;

    for (int e = warp_global; e < E; e += nwarps) {
        int row = __ldg(&ei[e]);
        int col = __ldg(&ei[(size_t)E + e]);

        const float4 v = *reinterpret_cast<const float4*>(
            &g_xs[(size_t)col * C + lane * 4]);
        float* dst = &g_agg[(size_t)row * C + lane * 4];
        asm volatile("red.global.add.v4.f32 [%0], {%1,%2,%3,%4};"
                     :: "l"(dst), "f"(v.x), "f"(v.y), "f"(v.z), "f"(v.w)
                     : "memory");
    }
}

// ---------------------------------------------------------------------------
// K5: fused epilogue + GEMM:  out = ((agg + xs) * rsqrt(deg+1)) @ W^T
// Block computes 64 rows x 128 cols. W transposed into padded smem
// (Wt[k][132], pad keeps 16B alignment of each row for conflict-free LDS.128).
// Thread tile: 8 rows x 4 cols (float4 accumulators).
// ---------------------------------------------------------------------------
#define RT 64
__global__ void __launch_bounds__(256) gemm_kernel(const float* __restrict__ W,
                                                   float* __restrict__ out,
                                                   int n) {
    extern __shared__ float sm[];
    float* Wt = sm;                 // [128][132]
    float* hs = sm + 128 * 132;     // [64][128]

    int tid = threadIdx.x;

    // Transpose W into smem (coalesced global read)
    #pragma unroll 4
    for (int idx = tid; idx < C * C; idx += 256) {
        int j = idx >> 7;      // out-channel
        int k = idx & 127;     // in-channel
        Wt[k * 132 + j] = W[idx];
    }

    // Build h-tile: h = (agg + xs) * rsqrt(deg+1)
    int row0 = blockIdx.x * RT;
    for (int idx = tid; idx < RT * 32; idx += 256) {
        int r = idx >> 5;
        int c4 = idx & 31;
        int row = row0 + r;
        float4 h = make_float4(0.f, 0.f, 0.f, 0.f);
        if (row < n) {
            float inv = rsqrtf(g_deg[row] + 1.0f);
            size_t off = (size_t)row * C + c4 * 4;
            float4 a  = *reinterpret_cast<const float4*>(&g_agg[off]);
            float4 xv = *reinterpret_cast<const float4*>(&g_xs[off]);
            h.x = (a.x + xv.x) * inv;
            h.y = (a.y + xv.y) * inv;
            h.z = (a.z + xv.z) * inv;
            h.w = (a.w + xv.w) * inv;
        }
        *reinterpret_cast<float4*>(&hs[r * C + c4 * 4]) = h;
    }
    __syncthreads();

    int lane = tid & 31;
    int warp = tid >> 5;            // warp w owns rows 8w..8w+7
    float4 acc[8];
    #pragma unroll
    for (int r = 0; r < 8; r++) acc[r] = make_float4(0.f, 0.f, 0.f, 0.f);

    #pragma unroll 1
    for (int k0 = 0; k0 < C; k0 += 4) {
        float4 wv0 = *reinterpret_cast<const float4*>(&Wt[(k0 + 0) * 132 + lane * 4]);
        float4 wv1 = *reinterpret_cast<const float4*>(&Wt[(k0 + 1) * 132 + lane * 4]);
        float4 wv2 = *reinterpret_cast<const float4*>(&Wt[(k0 + 2) * 132 + lane * 4]);
        float4 wv3 = *reinterpret_cast<const float4*>(&Wt[(k0 + 3) * 132 + lane * 4]);
        #pragma unroll
        for (int r = 0; r < 8; r++) {
            float4 hv = *reinterpret_cast<const float4*>(&hs[(warp * 8 + r) * C + k0]);
            acc[r].x += hv.x * wv0.x + hv.y * wv1.x + hv.z * wv2.x + hv.w * wv3.x;
            acc[r].y += hv.x * wv0.y + hv.y * wv1.y + hv.z * wv2.y + hv.w * wv3.y;
            acc[r].z += hv.x * wv0.z + hv.y * wv1.z + hv.z * wv2.z + hv.w * wv3.z;
            acc[r].w += hv.x * wv0.w + hv.y * wv1.w + hv.z * wv2.w + hv.w * wv3.w;
        }
    }

    #pragma unroll
    for (int r = 0; r < 8; r++) {
        int row = row0 + warp * 8 + r;
        if (row < n)
            *reinterpret_cast<float4*>(&out[(size_t)row * C + lane * 4]) = acc[r];
    }
}

// ---------------------------------------------------------------------------
// kernel_launch
// ---------------------------------------------------------------------------
extern "C" void kernel_launch(void* const* d_in, const int* in_sizes, int n_in,
                              void* d_out, int out_size) {
    const float* x  = (const float*)d_in[0];
    const int*   ei = (const int*)d_in[1];      // int32 (JAX x64 disabled)
    const float* W  = (const float*)d_in[2];
    float* out = (float*)d_out;

    int n = in_sizes[0] / C;        // 100000
    int E = in_sizes[1] / 2;        // 1600000

    const int T = 256;

    // K1: zero agg + deg
    zero_kernel<<<(n * 32 + T - 1) / T, T>>>(n);
    // K2: degree histogram
    deg_kernel<<<(E + T - 1) / T, T>>>(ei, E);
    // K3: xs = x * rsqrt(deg+1)
    xs_kernel<<<(n * 32 + T - 1) / T, T>>>(x, n);
    // K4: scatter-add (one warp per edge, grid-stride)
    scatter_kernel<<<8192, T>>>(ei, E);
    // K5: fused normalize + GEMM
    {
        int smem = (128 * 132 + RT * C) * sizeof(float);   // ~98 KB
        cudaFuncSetAttribute(gemm_kernel,
                             cudaFuncAttributeMaxDynamicSharedMemorySize, smem);
        int blocks = (n + RT - 1) / RT;
        gemm_kernel<<<blocks, T, smem>>>(W, out, n);
    }
}

// round 5
// speedup vs baseline: 1.3559x; 1.3559x over previous
#include <cuda_runtime.h>
#include <cuda_bf16.h>
#include <cstdint>

// Problem sizes (reference: N=100000, E=1600000, C=128)
#define MAXN 100000
#define MAXE 1600000
#define C 128

// Scratch (device globals — allocation-free per harness rules)
__device__ float g_xs[(size_t)MAXN * C];
__device__ float g_h[(size_t)MAXN * C];
__device__ int   g_ideg[MAXN];
__device__ int   g_rowstart[MAXN];
__device__ int   g_cur[MAXN];
__device__ int   g_csrcol[MAXE];
__device__ int   g_cursor;

// ---------------------------------------------------------------------------
// K0: init integer degree + allocation cursor
// ---------------------------------------------------------------------------
__global__ void init_kernel(int n) {
    int i = blockIdx.x * blockDim.x + threadIdx.x;
    if (i < n) g_ideg[i] = 0;
    if (i == 0) g_cursor = 0;
}

// ---------------------------------------------------------------------------
// K1: integer degree histogram over rows (edge_index[0])
// ---------------------------------------------------------------------------
__global__ void deg_kernel(const int* __restrict__ ei, int E) {
    int e = blockIdx.x * blockDim.x + threadIdx.x;
    if (e >= E) return;
    atomicAdd(&g_ideg[ei[e]], 1);
}

// ---------------------------------------------------------------------------
// K2: xs = x * rsqrt(deg+1)
// ---------------------------------------------------------------------------
__global__ void xs_kernel(const float* __restrict__ x, int n) {
    int idx = blockIdx.x * blockDim.x + threadIdx.x;   // n*32 float4 units
    if (idx >= n * 32) return;
    int row = idx >> 5;
    float inv = rsqrtf((float)g_ideg[row] + 1.0f);
    float4 v = *reinterpret_cast<const float4*>(&x[(size_t)idx * 4]);
    v.x *= inv; v.y *= inv; v.z *= inv; v.w *= inv;
    *reinterpret_cast<float4*>(&g_xs[(size_t)idx * 4]) = v;
}

// ---------------------------------------------------------------------------
// K3: allocate contiguous CSR segment per row.
// Block-aggregated bump allocation: intra-block exclusive scan of degrees
// (warp shuffle scan + smem warp totals), ONE atomicAdd of the block total
// on the global cursor per block (391 contended atomics instead of 100K).
// Segment ordering across blocks is arbitrary — the gather doesn't care.
// ---------------------------------------------------------------------------
__global__ void __launch_bounds__(256) alloc_kernel(int n) {
    __shared__ int warp_sums[8];
    __shared__ int block_base;

    int tid = threadIdx.x;
    int r = blockIdx.x * 256 + tid;
    int lane = tid & 31;
    int wid = tid >> 5;

    int d = (r < n) ? g_ideg[r] : 0;

    // warp-level inclusive scan
    int v = d;
    #pragma unroll
    for (int o = 1; o < 32; o <<= 1) {
        int t = __shfl_up_sync(0xFFFFFFFFu, v, o);
        if (lane >= o) v += t;
    }
    if (lane == 31) warp_sums[wid] = v;
    __syncthreads();

    // scan the 8 warp totals in warp 0
    if (wid == 0) {
        int s = (lane < 8) ? warp_sums[lane] : 0;
        #pragma unroll
        for (int o = 1; o < 8; o <<= 1) {
            int t = __shfl_up_sync(0xFFFFFFFFu, s, o);
            if (lane >= o) s += t;
        }
        if (lane < 8) warp_sums[lane] = s;       // inclusive warp prefixes
        if (lane == 7) block_base = atomicAdd(&g_cursor, s);  // block total
    }
    __syncthreads();

    int excl = v - d + (wid > 0 ? warp_sums[wid - 1] : 0) + block_base;
    if (r < n) {
        g_rowstart[r] = excl;
        g_cur[r] = excl;
    }
}

// ---------------------------------------------------------------------------
// K4: fill CSR column lists
// ---------------------------------------------------------------------------
__global__ void fill_kernel(const int* __restrict__ ei, int E) {
    int e = blockIdx.x * blockDim.x + threadIdx.x;
    if (e >= E) return;
    int row = ei[e];
    int col = ei[(size_t)E + e];
    int slot = atomicAdd(&g_cur[row], 1);
    g_csrcol[slot] = col;
}

// ---------------------------------------------------------------------------
// K5: aggregate (gather form): h[r] = (sum_{c in adj(r)} xs[c] + xs[r]) * inv
// One warp per row; each lane owns one float4 (16B) of the 512B row.
// Gathers are fully coalesced (all 32 lanes touch one contiguous xs row).
// Unrolled x2 for memory-level parallelism.
// ---------------------------------------------------------------------------
__global__ void __launch_bounds__(256) agg_kernel(int n) {
    int gtid = blockIdx.x * blockDim.x + threadIdx.x;
    int r = gtid >> 5;
    if (r >= n) return;
    int lane = gtid & 31;

    int start = g_rowstart[r];
    int deg = g_ideg[r];
    int end = start + deg;

    float4 acc0 = make_float4(0.f, 0.f, 0.f, 0.f);
    float4 acc1 = make_float4(0.f, 0.f, 0.f, 0.f);

    int i = start;
    for (; i + 1 < end; i += 2) {
        int c0 = __ldg(&g_csrcol[i]);
        int c1 = __ldg(&g_csrcol[i + 1]);
        float4 v0 = *reinterpret_cast<const float4*>(&g_xs[(size_t)c0 * C + lane * 4]);
        float4 v1 = *reinterpret_cast<const float4*>(&g_xs[(size_t)c1 * C + lane * 4]);
        acc0.x += v0.x; acc0.y += v0.y; acc0.z += v0.z; acc0.w += v0.w;
        acc1.x += v1.x; acc1.y += v1.y; acc1.z += v1.z; acc1.w += v1.w;
    }
    if (i < end) {
        int c0 = __ldg(&g_csrcol[i]);
        float4 v0 = *reinterpret_cast<const float4*>(&g_xs[(size_t)c0 * C + lane * 4]);
        acc0.x += v0.x; acc0.y += v0.y; acc0.z += v0.z; acc0.w += v0.w;
    }

    // + self contribution, then * rsqrt(deg+1)
    float inv = rsqrtf((float)deg + 1.0f);
    size_t off = (size_t)r * C + lane * 4;
    float4 own = *reinterpret_cast<const float4*>(&g_xs[off]);
    float4 h;
    h.x = (acc0.x + acc1.x + own.x) * inv;
    h.y = (acc0.y + acc1.y + own.y) * inv;
    h.z = (acc0.z + acc1.z + own.z) * inv;
    h.w = (acc0.w + acc1.w + own.w) * inv;
    *reinterpret_cast<float4*>(&g_h[off]) = h;
}

// ---------------------------------------------------------------------------
// K6: GEMM:  out = h @ W^T
// Block computes 64 rows x 128 cols. W transposed into padded smem
// (Wt[k][132]); h tile staged in smem. Thread tile: 8 rows x 4 cols.
// ---------------------------------------------------------------------------
#define RT 64
__global__ void __launch_bounds__(256) gemm_kernel(const float* __restrict__ W,
                                                   float* __restrict__ out,
                                                   int n) {
    extern __shared__ float sm[];
    float* Wt = sm;                 // [128][132]
    float* hs = sm + 128 * 132;     // [64][128]

    int tid = threadIdx.x;

    #pragma unroll 4
    for (int idx = tid; idx < C * C; idx += 256) {
        int j = idx >> 7;      // out-channel
        int k = idx & 127;     // in-channel
        Wt[k * 132 + j] = W[idx];
    }

    int row0 = blockIdx.x * RT;
    for (int idx = tid; idx < RT * 32; idx += 256) {
        int r = idx >> 5;
        int c4 = idx & 31;
        int row = row0 + r;
        float4 h = make_float4(0.f, 0.f, 0.f, 0.f);
        if (row < n)
            h = *reinterpret_cast<const float4*>(&g_h[(size_t)row * C + c4 * 4]);
        *reinterpret_cast<float4*>(&hs[r * C + c4 * 4]) = h;
    }
    __syncthreads();

    int lane = tid & 31;
    int warp = tid >> 5;            // warp w owns rows 8w..8w+7
    float4 acc[8];
    #pragma unroll
    for (int r = 0; r < 8; r++) acc[r] = make_float4(0.f, 0.f, 0.f, 0.f);

    #pragma unroll 1
    for (int k0 = 0; k0 < C; k0 += 4) {
        float4 wv0 = *reinterpret_cast<const float4*>(&Wt[(k0 + 0) * 132 + lane * 4]);
        float4 wv1 = *reinterpret_cast<const float4*>(&Wt[(k0 + 1) * 132 + lane * 4]);
        float4 wv2 = *reinterpret_cast<const float4*>(&Wt[(k0 + 2) * 132 + lane * 4]);
        float4 wv3 = *reinterpret_cast<const float4*>(&Wt[(k0 + 3) * 132 + lane * 4]);
        #pragma unroll
        for (int r = 0; r < 8; r++) {
            float4 hv = *reinterpret_cast<const float4*>(&hs[(warp * 8 + r) * C + k0]);
            acc[r].x += hv.x * wv0.x + hv.y * wv1.x + hv.z * wv2.x + hv.w * wv3.x;
            acc[r].y += hv.x * wv0.y + hv.y * wv1.y + hv.z * wv2.y + hv.w * wv3.y;
            acc[r].z += hv.x * wv0.z + hv.y * wv1.z + hv.z * wv2.z + hv.w * wv3.z;
            acc[r].w += hv.x * wv0.w + hv.y * wv1.w + hv.z * wv2.w + hv.w * wv3.w;
        }
    }

    #pragma unroll
    for (int r = 0; r < 8; r++) {
        int row = row0 + warp * 8 + r;
        if (row < n)
            *reinterpret_cast<float4*>(&out[(size_t)row * C + lane * 4]) = acc[r];
    }
}

// ---------------------------------------------------------------------------
// kernel_launch
// ---------------------------------------------------------------------------
extern "C" void kernel_launch(void* const* d_in, const int* in_sizes, int n_in,
                              void* d_out, int out_size) {
    const float* x  = (const float*)d_in[0];
    const int*   ei = (const int*)d_in[1];      // int32 (JAX x64 disabled)
    const float* W  = (const float*)d_in[2];
    float* out = (float*)d_out;

    int n = in_sizes[0] / C;        // 100000
    int E = in_sizes[1] / 2;        // 1600000

    const int T = 256;

    init_kernel<<<(n + T - 1) / T, T>>>(n);
    deg_kernel<<<(E + T - 1) / T, T>>>(ei, E);
    xs_kernel<<<(n * 32 + T - 1) / T, T>>>(x, n);
    alloc_kernel<<<(n + 255) / 256, 256>>>(n);
    fill_kernel<<<(E + T - 1) / T, T>>>(ei, E);
    agg_kernel<<<(n * 32 + T - 1) / T, T>>>(n);
    {
        int smem = (128 * 132 + RT * C) * sizeof(float);   // ~98 KB
        cudaFuncSetAttribute(gemm_kernel,
                             cudaFuncAttributeMaxDynamicSharedMemorySize, smem);
        int blocks = (n + RT - 1) / RT;
        gemm_kernel<<<blocks, T, smem>>>(W, out, n);
    }
}

// round 6
// speedup vs baseline: 1.3794x; 1.0174x over previous
#include <cuda_runtime.h>
#include <cuda_bf16.h>
#include <cstdint>

// Problem sizes (reference: N=100000, E=1600000, C=128)
#define MAXN 100000
#define MAXE 1600000
#define C 128

// Scratch (device globals — allocation-free per harness rules)
__device__ float  g_xs[(size_t)MAXN * C];
__device__ int    g_ideg[MAXN];
__device__ int    g_rowstart[MAXN];
__device__ int    g_cur[MAXN];
__device__ int    g_csrcol[MAXE];
__device__ int    g_cursor;
__device__ float2 g_Wp[64 * 128];   // [kp][j] = (W[j][2kp], W[j][2kp+1])

// packed-f32x2 FMA: acc(2xf32) += a(2xf32) * b(2xf32)
#define FMA2(acc, a, b) \
    asm("fma.rn.f32x2 %0, %1, %2, %0;" : "+l"(acc) : "l"(a), "l"(b))

__device__ __forceinline__ float pairsum(unsigned long long v) {
    float lo, hi;
    asm("mov.b64 {%0, %1}, %2;" : "=f"(lo), "=f"(hi) : "l"(v));
    return lo + hi;
}

// ---------------------------------------------------------------------------
// K0: init integer degree + allocation cursor
// ---------------------------------------------------------------------------
__global__ void init_kernel(int n) {
    int i = blockIdx.x * blockDim.x + threadIdx.x;
    if (i < n) g_ideg[i] = 0;
    if (i == 0) g_cursor = 0;
}

// ---------------------------------------------------------------------------
// K1: integer degree histogram over rows (edge_index[0])
// ---------------------------------------------------------------------------
__global__ void deg_kernel(const int* __restrict__ ei, int E) {
    int e = blockIdx.x * blockDim.x + threadIdx.x;
    if (e >= E) return;
    atomicAdd(&g_ideg[ei[e]], 1);
}

// ---------------------------------------------------------------------------
// K2: xs = x * rsqrt(deg+1)
// ---------------------------------------------------------------------------
__global__ void xs_kernel(const float* __restrict__ x, int n) {
    int idx = blockIdx.x * blockDim.x + threadIdx.x;   // n*32 float4 units
    if (idx >= n * 32) return;
    int row = idx >> 5;
    float inv = rsqrtf((float)g_ideg[row] + 1.0f);
    float4 v = *reinterpret_cast<const float4*>(&x[(size_t)idx * 4]);
    v.x *= inv; v.y *= inv; v.z *= inv; v.w *= inv;
    *reinterpret_cast<float4*>(&g_xs[(size_t)idx * 4]) = v;
}

// ---------------------------------------------------------------------------
// K3: CSR segment allocation — block-aggregated bump allocation (one global
// atomic per block of 256 rows; intra-block exclusive scan via shuffles).
// ---------------------------------------------------------------------------
__global__ void __launch_bounds__(256) alloc_kernel(int n) {
    __shared__ int warp_sums[8];
    __shared__ int block_base;

    int tid = threadIdx.x;
    int r = blockIdx.x * 256 + tid;
    int lane = tid & 31;
    int wid = tid >> 5;

    int d = (r < n) ? g_ideg[r] : 0;

    int v = d;
    #pragma unroll
    for (int o = 1; o < 32; o <<= 1) {
        int t = __shfl_up_sync(0xFFFFFFFFu, v, o);
        if (lane >= o) v += t;
    }
    if (lane == 31) warp_sums[wid] = v;
    __syncthreads();

    if (wid == 0) {
        int s = (lane < 8) ? warp_sums[lane] : 0;
        #pragma unroll
        for (int o = 1; o < 8; o <<= 1) {
            int t = __shfl_up_sync(0xFFFFFFFFu, s, o);
            if (lane >= o) s += t;
        }
        if (lane < 8) warp_sums[lane] = s;
        if (lane == 7) block_base = atomicAdd(&g_cursor, s);
    }
    __syncthreads();

    int excl = v - d + (wid > 0 ? warp_sums[wid - 1] : 0) + block_base;
    if (r < n) {
        g_rowstart[r] = excl;
        g_cur[r] = excl;
    }
}

// ---------------------------------------------------------------------------
// K4: fill CSR column lists
// ---------------------------------------------------------------------------
__global__ void fill_kernel(const int* __restrict__ ei, int E) {
    int e = blockIdx.x * blockDim.x + threadIdx.x;
    if (e >= E) return;
    int row = ei[e];
    int col = ei[(size_t)E + e];
    int slot = atomicAdd(&g_cur[row], 1);
    g_csrcol[slot] = col;
}

// ---------------------------------------------------------------------------
// K5: W pre-swizzle (once, tiny): g_Wp[kp][j] = (W[j][2kp], W[j][2kp+1]).
// Lets the GEMM load k-paired W operands coalesced & conflict-free.
// ---------------------------------------------------------------------------
__global__ void wprep_kernel(const float* __restrict__ W) {
    int idx = blockIdx.x * blockDim.x + threadIdx.x;
    if (idx >= 64 * 128) return;
    int kp = idx >> 7;
    int j  = idx & 127;
    g_Wp[idx] = *reinterpret_cast<const float2*>(&W[j * C + kp * 2]);
}

// ---------------------------------------------------------------------------
// K6: FUSED aggregate + GEMM.
// Phase A: each warp gathers/normalizes 8 rows into smem hs[64][128].
// Phase B: f32x2-packed GEMM over k-pairs; accumulator = (sum_even_k,
// sum_odd_k), halves folded in the epilogue. Thread tile: 8 rows x 4 cols.
// smem: Wp 64KB + hs 32KB = 96KB.
// ---------------------------------------------------------------------------
#define RT 64
__global__ void __launch_bounds__(256) fused_kernel(float* __restrict__ out,
                                                    int n) {
    extern __shared__ char sm_raw[];
    float2* Wp = reinterpret_cast<float2*>(sm_raw);           // [64][128]
    float*  hs = reinterpret_cast<float*>(sm_raw + 65536);    // [64][128]

    int tid = threadIdx.x;
    int lane = tid & 31;
    int warp = tid >> 5;

    // ---- stage Wp (coalesced global float2, consecutive smem) ----
    {
        const float2* src = g_Wp;
        #pragma unroll
        for (int i = 0; i < 32; i++)                  // 8192 / 256
            Wp[tid + i * 256] = src[tid + i * 256];
    }

    // ---- phase A: aggregate 64 rows into hs ----
    int row0 = blockIdx.x * RT;
    for (int r = warp; r < RT; r += 8) {
        int row = row0 + r;
        float4 h = make_float4(0.f, 0.f, 0.f, 0.f);
        if (row < n) {
            int start = g_rowstart[row];
            int deg = g_ideg[row];
            int end = start + deg;
            float4 a0 = make_float4(0.f, 0.f, 0.f, 0.f);
            float4 a1 = make_float4(0.f, 0.f, 0.f, 0.f);
            int i = start;
            for (; i + 1 < end; i += 2) {
                int c0 = __ldg(&g_csrcol[i]);
                int c1 = __ldg(&g_csrcol[i + 1]);
                float4 v0 = *reinterpret_cast<const float4*>(
                    &g_xs[(size_t)c0 * C + lane * 4]);
                float4 v1 = *reinterpret_cast<const float4*>(
                    &g_xs[(size_t)c1 * C + lane * 4]);
                a0.x += v0.x; a0.y += v0.y; a0.z += v0.z; a0.w += v0.w;
                a1.x += v1.x; a1.y += v1.y; a1.z += v1.z; a1.w += v1.w;
            }
            if (i < end) {
                int c0 = __ldg(&g_csrcol[i]);
                float4 v0 = *reinterpret_cast<const float4*>(
                    &g_xs[(size_t)c0 * C + lane * 4]);
                a0.x += v0.x; a0.y += v0.y; a0.z += v0.z; a0.w += v0.w;
            }
            float inv = rsqrtf((float)deg + 1.0f);
            float4 own = *reinterpret_cast<const float4*>(
                &g_xs[(size_t)row * C + lane * 4]);
            h.x = (a0.x + a1.x + own.x) * inv;
            h.y = (a0.y + a1.y + own.y) * inv;
            h.z = (a0.z + a1.z + own.z) * inv;
            h.w = (a0.w + a1.w + own.w) * inv;
        }
        *reinterpret_cast<float4*>(&hs[r * C + lane * 4]) = h;
    }
    __syncthreads();

    // ---- phase B: packed GEMM ----
    unsigned long long acc[8][4];
    #pragma unroll
    for (int r = 0; r < 8; r++)
        #pragma unroll
        for (int j = 0; j < 4; j++) acc[r][j] = 0ULL;

    #pragma unroll 2
    for (int kp = 0; kp < 64; kp += 2) {
        // W pairs for 4 output cols, at kp and kp+1 (conflict-free LDS128)
        ulonglong2 w0 = *reinterpret_cast<const ulonglong2*>(
            &Wp[kp * 128 + lane * 4]);
        ulonglong2 w1 = *reinterpret_cast<const ulonglong2*>(
            &Wp[kp * 128 + lane * 4 + 2]);
        ulonglong2 w2 = *reinterpret_cast<const ulonglong2*>(
            &Wp[(kp + 1) * 128 + lane * 4]);
        ulonglong2 w3 = *reinterpret_cast<const ulonglong2*>(
            &Wp[(kp + 1) * 128 + lane * 4 + 2]);
        #pragma unroll
        for (int r = 0; r < 8; r++) {
            // h-pairs for kp (hp.x) and kp+1 (hp.y) — broadcast LDS128
            ulonglong2 hp = *reinterpret_cast<const ulonglong2*>(
                &hs[(warp * 8 + r) * C + kp * 2]);
            FMA2(acc[r][0], hp.x, w0.x); FMA2(acc[r][0], hp.y, w2.x);
            FMA2(acc[r][1], hp.x, w0.y); FMA2(acc[r][1], hp.y, w2.y);
            FMA2(acc[r][2], hp.x, w1.x); FMA2(acc[r][2], hp.y, w3.x);
            FMA2(acc[r][3], hp.x, w1.y); FMA2(acc[r][3], hp.y, w3.y);
        }
    }

    // ---- epilogue: fold halves, write float4 ----
    #pragma unroll
    for (int r = 0; r < 8; r++) {
        int row = row0 + warp * 8 + r;
        if (row >= n) continue;
        float4 o;
        o.x = pairsum(acc[r][0]);
        o.y = pairsum(acc[r][1]);
        o.z = pairsum(acc[r][2]);
        o.w = pairsum(acc[r][3]);
        *reinterpret_cast<float4*>(&out[(size_t)row * C + lane * 4]) = o;
    }
}

// ---------------------------------------------------------------------------
// kernel_launch
// ---------------------------------------------------------------------------
extern "C" void kernel_launch(void* const* d_in, const int* in_sizes, int n_in,
                              void* d_out, int out_size) {
    const float* x  = (const float*)d_in[0];
    const int*   ei = (const int*)d_in[1];      // int32 (JAX x64 disabled)
    const float* W  = (const float*)d_in[2];
    float* out = (float*)d_out;

    int n = in_sizes[0] / C;        // 100000
    int E = in_sizes[1] / 2;        // 1600000

    const int T = 256;

    init_kernel<<<(n + T - 1) / T, T>>>(n);
    deg_kernel<<<(E + T - 1) / T, T>>>(ei, E);
    xs_kernel<<<(n * 32 + T - 1) / T, T>>>(x, n);
    alloc_kernel<<<(n + 255) / 256, 256>>>(n);
    fill_kernel<<<(E + T - 1) / T, T>>>(ei, E);
    wprep_kernel<<<(64 * 128 + T - 1) / T, T>>>(W);
    {
        int smem = 65536 + RT * C * (int)sizeof(float);   // 96 KB
        cudaFuncSetAttribute(fused_kernel,
                             cudaFuncAttributeMaxDynamicSharedMemorySize, smem);
        int blocks = (n + RT - 1) / RT;
        fused_kernel<<<blocks, T, smem>>>(out, n);
    }
}

// round 9
// speedup vs baseline: 1.4036x; 1.0175x over previous
#include <cuda_runtime.h>
#include <cuda_bf16.h>
#include <cstdint>

// Problem sizes (reference: N=100000, E=1600000, C=128)
#define MAXN 100000
#define MAXE 1600000
#define C 128

// Scratch (device globals — allocation-free per harness rules)
__device__ float  g_xs[(size_t)MAXN * C];
__device__ float  g_h[(size_t)MAXN * C];
__device__ int    g_ideg[MAXN];
__device__ int    g_rowstart[MAXN];
__device__ int    g_cur[MAXN];
__device__ int    g_csrcol[MAXE];
__device__ int    g_cursor;
__device__ float2 g_Wp[64 * 128];   // [kp][j] = (W[j][2kp], W[j][2kp+1])

// packed-f32x2 FMA: acc(2xf32) += a(2xf32) * b(2xf32)
#define FMA2(acc, a, b) \
    asm("fma.rn.f32x2 %0, %1, %2, %0;" : "+l"(acc) : "l"(a), "l"(b))

__device__ __forceinline__ float pairsum(unsigned long long v) {
    float lo, hi;
    asm("mov.b64 {%0, %1}, %2;" : "=f"(lo), "=f"(hi) : "l"(v));
    return lo + hi;
}

// ---------------------------------------------------------------------------
// K0: init integer degree + cursor, and pre-swizzle W into k-paired layout
// g_Wp[kp][j] = (W[j][2kp], W[j][2kp+1]).  (independent jobs, one grid)
// ---------------------------------------------------------------------------
__global__ void init_kernel(const float* __restrict__ W, int n) {
    int i = blockIdx.x * blockDim.x + threadIdx.x;
    if (i < n) g_ideg[i] = 0;
    if (i == 0) g_cursor = 0;
    if (i < 64 * 128) {
        int kp = i >> 7;
        int j  = i & 127;
        g_Wp[i] = *reinterpret_cast<const float2*>(&W[j * C + kp * 2]);
    }
}

// ---------------------------------------------------------------------------
// K1: integer degree histogram over rows (edge_index[0])
// ---------------------------------------------------------------------------
__global__ void deg_kernel(const int* __restrict__ ei, int E) {
    int e = blockIdx.x * blockDim.x + threadIdx.x;
    if (e >= E) return;
    atomicAdd(&g_ideg[__ldg(&ei[e])], 1);
}

// ---------------------------------------------------------------------------
// K2: xs = x * rsqrt(deg+1)
// ---------------------------------------------------------------------------
__global__ void xs_kernel(const float* __restrict__ x, int n) {
    int idx = blockIdx.x * blockDim.x + threadIdx.x;   // n*32 float4 units
    if (idx >= n * 32) return;
    int row = idx >> 5;
    float inv = rsqrtf((float)g_ideg[row] + 1.0f);
    float4 v = *reinterpret_cast<const float4*>(&x[(size_t)idx * 4]);
    v.x *= inv; v.y *= inv; v.z *= inv; v.w *= inv;
    *reinterpret_cast<float4*>(&g_xs[(size_t)idx * 4]) = v;
}

// ---------------------------------------------------------------------------
// K3: CSR segment allocation — block-aggregated bump allocation (one global
// atomic per block of 256 rows; intra-block exclusive scan via shuffles).
// ---------------------------------------------------------------------------
__global__ void __launch_bounds__(256) alloc_kernel(int n) {
    __shared__ int warp_sums[8];
    __shared__ int block_base;

    int tid = threadIdx.x;
    int r = blockIdx.x * 256 + tid;
    int lane = tid & 31;
    int wid = tid >> 5;

    int d = (r < n) ? g_ideg[r] : 0;

    int v = d;
    #pragma unroll
    for (int o = 1; o < 32; o <<= 1) {
        int t = __shfl_up_sync(0xFFFFFFFFu, v, o);
        if (lane >= o) v += t;
    }
    if (lane == 31) warp_sums[wid] = v;
    __syncthreads();

    if (wid == 0) {
        int s = (lane < 8) ? warp_sums[lane] : 0;
        #pragma unroll
        for (int o = 1; o < 8; o <<= 1) {
            int t = __shfl_up_sync(0xFFFFFFFFu, s, o);
            if (lane >= o) s += t;
        }
        if (lane < 8) warp_sums[lane] = s;
        if (lane == 7) block_base = atomicAdd(&g_cursor, s);
    }
    __syncthreads();

    int excl = v - d + (wid > 0 ? warp_sums[wid - 1] : 0) + block_base;
    if (r < n) {
        g_rowstart[r] = excl;
        g_cur[r] = excl;
    }
}

// ---------------------------------------------------------------------------
// K4: fill CSR column lists
// ---------------------------------------------------------------------------
__global__ void fill_kernel(const int* __restrict__ ei, int E) {
    int e = blockIdx.x * blockDim.x + threadIdx.x;
    if (e >= E) return;
    int row = __ldg(&ei[e]);
    int col = __ldg(&ei[(size_t)E + e]);
    int slot = atomicAdd(&g_cur[row], 1);
    g_csrcol[slot] = col;
}

// ---------------------------------------------------------------------------
// K5: aggregate (gather, high occupancy, unroll-4 for MLP):
// h[r] = (sum_{c in adj(r)} xs[c] + xs[r]) * rsqrt(deg+1)
// One warp per row, no smem -> full occupancy hides L2 latency.
// ---------------------------------------------------------------------------
__global__ void __launch_bounds__(256) agg_kernel(int n) {
    int gtid = blockIdx.x * blockDim.x + threadIdx.x;
    int r = gtid >> 5;
    if (r >= n) return;
    int lane = gtid & 31;

    int start = g_rowstart[r];
    int deg = g_ideg[r];
    int end = start + deg;

    float4 a0 = make_float4(0.f, 0.f, 0.f, 0.f);
    float4 a1 = make_float4(0.f, 0.f, 0.f, 0.f);
    float4 a2 = make_float4(0.f, 0.f, 0.f, 0.f);
    float4 a3 = make_float4(0.f, 0.f, 0.f, 0.f);

    int i = start;
    for (; i + 3 < end; i += 4) {
        int c0 = __ldg(&g_csrcol[i]);
        int c1 = __ldg(&g_csrcol[i + 1]);
        int c2 = __ldg(&g_csrcol[i + 2]);
        int c3 = __ldg(&g_csrcol[i + 3]);
        float4 v0 = *reinterpret_cast<const float4*>(&g_xs[(size_t)c0 * C + lane * 4]);
        float4 v1 = *reinterpret_cast<const float4*>(&g_xs[(size_t)c1 * C + lane * 4]);
        float4 v2 = *reinterpret_cast<const float4*>(&g_xs[(size_t)c2 * C + lane * 4]);
        float4 v3 = *reinterpret_cast<const float4*>(&g_xs[(size_t)c3 * C + lane * 4]);
        a0.x += v0.x; a0.y += v0.y; a0.z += v0.z; a0.w += v0.w;
        a1.x += v1.x; a1.y += v1.y; a1.z += v1.z; a1.w += v1.w;
        a2.x += v2.x; a2.y += v2.y; a2.z += v2.z; a2.w += v2.w;
        a3.x += v3.x; a3.y += v3.y; a3.z += v3.z; a3.w += v3.w;
    }
    for (; i < end; i++) {
        int c0 = __ldg(&g_csrcol[i]);
        float4 v0 = *reinterpret_cast<const float4*>(&g_xs[(size_t)c0 * C + lane * 4]);
        a0.x += v0.x; a0.y += v0.y; a0.z += v0.z; a0.w += v0.w;
    }

    float inv = rsqrtf((float)deg + 1.0f);
    size_t off = (size_t)r * C + lane * 4;
    float4 own = *reinterpret_cast<const float4*>(&g_xs[off]);
    float4 h;
    h.x = (a0.x + a1.x + a2.x + a3.x + own.x) * inv;
    h.y = (a0.y + a1.y + a2.y + a3.y + own.y) * inv;
    h.z = (a0.z + a1.z + a2.z + a3.z + own.z) * inv;
    h.w = (a0.w + a1.w + a2.w + a3.w + own.w) * inv;
    *reinterpret_cast<float4*>(&g_h[off]) = h;
}

// ---------------------------------------------------------------------------
// K6: f32x2-packed GEMM: out = h @ W^T.
// Block: 64 rows x 128 cols; thread tile 8 rows x 4 cols, k packed in pairs
// (acc = (sum_even_k, sum_odd_k), folded at epilogue).
// smem: Wp 64KB + hs 32KB = 96KB (2 CTAs/SM).
// ---------------------------------------------------------------------------
#define RT 64
__global__ void __launch_bounds__(256) gemm_kernel(float* __restrict__ out,
                                                   int n) {
    extern __shared__ char sm_raw[];
    float2* Wp = reinterpret_cast<float2*>(sm_raw);           // [64][128]
    float*  hs = reinterpret_cast<float*>(sm_raw + 65536);    // [64][128]

    int tid = threadIdx.x;
    int lane = tid & 31;
    int warp = tid >> 5;

    // stage Wp (coalesced)
    {
        const float2* src = g_Wp;
        #pragma unroll
        for (int i = 0; i < 32; i++)                  // 8192 / 256
            Wp[tid + i * 256] = src[tid + i * 256];
    }

    // stage hs (coalesced float4)
    int row0 = blockIdx.x * RT;
    for (int idx = tid; idx < RT * 32; idx += 256) {
        int r = idx >> 5;
        int c4 = idx & 31;
        int row = row0 + r;
        float4 h = make_float4(0.f, 0.f, 0.f, 0.f);
        if (row < n)
            h = *reinterpret_cast<const float4*>(&g_h[(size_t)row * C + c4 * 4]);
        *reinterpret_cast<float4*>(&hs[r * C + c4 * 4]) = h;
    }
    __syncthreads();

    unsigned long long acc[8][4];
    #pragma unroll
    for (int r = 0; r < 8; r++)
        #pragma unroll
        for (int j = 0; j < 4; j++) acc[r][j] = 0ULL;

    for (int kp = 0; kp < 64; kp += 2) {
        ulonglong2 w0 = *reinterpret_cast<const ulonglong2*>(
            &Wp[kp * 128 + lane * 4]);
        ulonglong2 w1 = *reinterpret_cast<const ulonglong2*>(
            &Wp[kp * 128 + lane * 4 + 2]);
        ulonglong2 w2 = *reinterpret_cast<const ulonglong2*>(
            &Wp[(kp + 1) * 128 + lane * 4]);
        ulonglong2 w3 = *reinterpret_cast<const ulonglong2*>(
            &Wp[(kp + 1) * 128 + lane * 4 + 2]);
        #pragma unroll
        for (int r = 0; r < 8; r++) {
            ulonglong2 hp = *reinterpret_cast<const ulonglong2*>(
                &hs[(warp * 8 + r) * C + kp * 2]);
            FMA2(acc[r][0], hp.x, w0.x); FMA2(acc[r][0], hp.y, w2.x);
            FMA2(acc[r][1], hp.x, w0.y); FMA2(acc[r][1], hp.y, w2.y);
            FMA2(acc[r][2], hp.x, w1.x); FMA2(acc[r][2], hp.y, w3.x);
            FMA2(acc[r][3], hp.x, w1.y); FMA2(acc[r][3], hp.y, w3.y);
        }
    }

    #pragma unroll
    for (int r = 0; r < 8; r++) {
        int row = row0 + warp * 8 + r;
        if (row >= n) continue;
        float4 o;
        o.x = pairsum(acc[r][0]);
        o.y = pairsum(acc[r][1]);
        o.z = pairsum(acc[r][2]);
        o.w = pairsum(acc[r][3]);
        *reinterpret_cast<float4*>(&out[(size_t)row * C + lane * 4]) = o;
    }
}

// ---------------------------------------------------------------------------
// kernel_launch
// ---------------------------------------------------------------------------
extern "C" void kernel_launch(void* const* d_in, const int* in_sizes, int n_in,
                              void* d_out, int out_size) {
    const float* x  = (const float*)d_in[0];
    const int*   ei = (const int*)d_in[1];      // int32 (JAX x64 disabled)
    const float* W  = (const float*)d_in[2];
    float* out = (float*)d_out;

    int n = in_sizes[0] / C;        // 100000
    int E = in_sizes[1] / 2;        // 1600000

    const int T = 256;

    init_kernel<<<(n + T - 1) / T, T>>>(W, n);
    deg_kernel<<<(E + T - 1) / T, T>>>(ei, E);
    xs_kernel<<<(n * 32 + T - 1) / T, T>>>(x, n);
    alloc_kernel<<<(n + 255) / 256, 256>>>(n);
    fill_kernel<<<(E + T - 1) / T, T>>>(ei, E);
    agg_kernel<<<(n * 32 + T - 1) / T, T>>>(n);
    {
        int smem = 65536 + RT * C * (int)sizeof(float);   // 96 KB
        cudaFuncSetAttribute(gemm_kernel,
                             cudaFuncAttributeMaxDynamicSharedMemorySize, smem);
        int blocks = (n + RT - 1) / RT;
        gemm_kernel<<<blocks, T, smem>>>(out, n);
    }
}

// round 12
// speedup vs baseline: 1.4944x; 1.0646x over previous
#include <cuda_runtime.h>
#include <cuda_bf16.h>
#include <cstdint>

// GCNConv pipeline, CSR-gather formulation. Round 12 resubmission of the
// round-10 kernel (two broker-level container failures; no kernel signal).
//
// Stages:
//   K0 init+Wprep -> K1 deg -> K2 xs -> K3 alloc -> K4 fill -> K5 agg -> K6 gemm
//
// Problem sizes (reference: N=100000, E=1600000, C=128)
#define MAXN 100000
#define MAXE 1600000
#define C 128

// Scratch (device globals — allocation-free per harness rules)
__device__ float  g_xs[(size_t)MAXN * C];
__device__ float  g_h[(size_t)MAXN * C];
__device__ int    g_ideg[MAXN];
__device__ int    g_rowstart[MAXN];
__device__ int    g_cur[MAXN];
__device__ int    g_csrcol[MAXE];
__device__ int    g_cursor;
__device__ float2 g_Wp[64 * 128];   // [kp][j] = (W[j][2kp], W[j][2kp+1])

// packed-f32x2 FMA: acc(2xf32) += a(2xf32) * b(2xf32)
#define FMA2(acc, a, b) \
    asm("fma.rn.f32x2 %0, %1, %2, %0;" : "+l"(acc) : "l"(a), "l"(b))

__device__ __forceinline__ float pairsum(unsigned long long v) {
    float lo, hi;
    asm("mov.b64 {%0, %1}, %2;" : "=f"(lo), "=f"(hi) : "l"(v));
    return lo + hi;
}

// ---------------------------------------------------------------------------
// K0: init degree counters + cursor; pre-swizzle W into k-paired layout.
// ---------------------------------------------------------------------------
__global__ void init_kernel(const float* __restrict__ W, int n) {
    int i = blockIdx.x * blockDim.x + threadIdx.x;
    if (i < n) g_ideg[i] = 0;
    if (i == 0) g_cursor = 0;
    if (i < 64 * 128) {
        int kp = i >> 7;
        int j  = i & 127;
        g_Wp[i] = *reinterpret_cast<const float2*>(&W[j * C + kp * 2]);
    }
}

// ---------------------------------------------------------------------------
// K1: integer degree histogram over rows (edge_index[0]).
// ---------------------------------------------------------------------------
__global__ void deg_kernel(const int* __restrict__ ei, int E) {
    int e = blockIdx.x * blockDim.x + threadIdx.x;
    if (e >= E) return;
    atomicAdd(&g_ideg[__ldg(&ei[e])], 1);
}

// ---------------------------------------------------------------------------
// K2: xs = x * rsqrt(deg+1).
// ---------------------------------------------------------------------------
__global__ void xs_kernel(const float* __restrict__ x, int n) {
    int idx = blockIdx.x * blockDim.x + threadIdx.x;   // n*32 float4 units
    if (idx >= n * 32) return;
    int row = idx >> 5;
    float inv = rsqrtf((float)g_ideg[row] + 1.0f);
    float4 v = *reinterpret_cast<const float4*>(&x[(size_t)idx * 4]);
    v.x *= inv; v.y *= inv; v.z *= inv; v.w *= inv;
    *reinterpret_cast<float4*>(&g_xs[(size_t)idx * 4]) = v;
}

// ---------------------------------------------------------------------------
// K3: CSR segment allocation — block-aggregated bump allocation.
// One contended global atomic per 256-row block; shuffle scans inside.
// ---------------------------------------------------------------------------
__global__ void __launch_bounds__(256) alloc_kernel(int n) {
    __shared__ int warp_sums[8];
    __shared__ int block_base;

    int tid = threadIdx.x;
    int r = blockIdx.x * 256 + tid;
    int lane = tid & 31;
    int wid = tid >> 5;

    int d = (r < n) ? g_ideg[r] : 0;

    int v = d;
    #pragma unroll
    for (int o = 1; o < 32; o <<= 1) {
        int t = __shfl_up_sync(0xFFFFFFFFu, v, o);
        if (lane >= o) v += t;
    }
    if (lane == 31) warp_sums[wid] = v;
    __syncthreads();

    if (wid == 0) {
        int s = (lane < 8) ? warp_sums[lane] : 0;
        #pragma unroll
        for (int o = 1; o < 8; o <<= 1) {
            int t = __shfl_up_sync(0xFFFFFFFFu, s, o);
            if (lane >= o) s += t;
        }
        if (lane < 8) warp_sums[lane] = s;
        if (lane == 7) block_base = atomicAdd(&g_cursor, s);
    }
    __syncthreads();

    int excl = v - d + (wid > 0 ? warp_sums[wid - 1] : 0) + block_base;
    if (r < n) {
        g_rowstart[r] = excl;
        g_cur[r] = excl;
    }
}

// ---------------------------------------------------------------------------
// K4: fill CSR column lists.
// ---------------------------------------------------------------------------
__global__ void fill_kernel(const int* __restrict__ ei, int E) {
    int e = blockIdx.x * blockDim.x + threadIdx.x;
    if (e >= E) return;
    int row = __ldg(&ei[e]);
    int col = __ldg(&ei[(size_t)E + e]);
    int slot = atomicAdd(&g_cur[row], 1);
    g_csrcol[slot] = col;
}

// ---------------------------------------------------------------------------
// K5: aggregate (gather): h[r] = (sum_{c in adj(r)} xs[c] + xs[r]) * inv.
// One warp per row, zero smem (full occupancy), unroll-4 for MLP.
// ---------------------------------------------------------------------------
__global__ void __launch_bounds__(256) agg_kernel(int n) {
    int gtid = blockIdx.x * blockDim.x + threadIdx.x;
    int r = gtid >> 5;
    if (r >= n) return;
    int lane = gtid & 31;

    int start = g_rowstart[r];
    int deg = g_ideg[r];
    int end = start + deg;

    float4 a0 = make_float4(0.f, 0.f, 0.f, 0.f);
    float4 a1 = make_float4(0.f, 0.f, 0.f, 0.f);
    float4 a2 = make_float4(0.f, 0.f, 0.f, 0.f);
    float4 a3 = make_float4(0.f, 0.f, 0.f, 0.f);

    int i = start;
    for (; i + 3 < end; i += 4) {
        int c0 = __ldg(&g_csrcol[i]);
        int c1 = __ldg(&g_csrcol[i + 1]);
        int c2 = __ldg(&g_csrcol[i + 2]);
        int c3 = __ldg(&g_csrcol[i + 3]);
        float4 v0 = *reinterpret_cast<const float4*>(&g_xs[(size_t)c0 * C + lane * 4]);
        float4 v1 = *reinterpret_cast<const float4*>(&g_xs[(size_t)c1 * C + lane * 4]);
        float4 v2 = *reinterpret_cast<const float4*>(&g_xs[(size_t)c2 * C + lane * 4]);
        float4 v3 = *reinterpret_cast<const float4*>(&g_xs[(size_t)c3 * C + lane * 4]);
        a0.x += v0.x; a0.y += v0.y; a0.z += v0.z; a0.w += v0.w;
        a1.x += v1.x; a1.y += v1.y; a1.z += v1.z; a1.w += v1.w;
        a2.x += v2.x; a2.y += v2.y; a2.z += v2.z; a2.w += v2.w;
        a3.x += v3.x; a3.y += v3.y; a3.z += v3.z; a3.w += v3.w;
    }
    for (; i < end; i++) {
        int c0 = __ldg(&g_csrcol[i]);
        float4 v0 = *reinterpret_cast<const float4*>(&g_xs[(size_t)c0 * C + lane * 4]);
        a0.x += v0.x; a0.y += v0.y; a0.z += v0.z; a0.w += v0.w;
    }

    float inv = rsqrtf((float)deg + 1.0f);
    size_t off = (size_t)r * C + lane * 4;
    float4 own = *reinterpret_cast<const float4*>(&g_xs[off]);
    float4 h;
    h.x = (a0.x + a1.x + a2.x + a3.x + own.x) * inv;
    h.y = (a0.y + a1.y + a2.y + a3.y + own.y) * inv;
    h.z = (a0.z + a1.z + a2.z + a3.z + own.z) * inv;
    h.w = (a0.w + a1.w + a2.w + a3.w + own.w) * inv;
    *reinterpret_cast<float4*>(&g_h[off]) = h;
}

// ---------------------------------------------------------------------------
// K6: f32x2-packed GEMM: out = h @ W^T.
// Thread tile 8 rows x 4 cols with cols strided by 32 (col = lane + 32*jg):
// W k-pair loads become conflict-free LDS.64 (8B lane stride, 256B/warp),
// putting the kernel on the FFMA2 pipe floor instead of being LDS-bound
// (the round-9 version's lane*4 mapping was 2-way conflicted LDS.128).
// k packed in pairs: acc = (sum_even_k, sum_odd_k), folded at epilogue.
// smem: Wp 64KB + hs 32KB = 96KB (2 CTAs/SM).
// ---------------------------------------------------------------------------
#define RT 64
__global__ void __launch_bounds__(256) gemm_kernel(float* __restrict__ out,
                                                   int n) {
    extern __shared__ char sm_raw[];
    float2* Wp = reinterpret_cast<float2*>(sm_raw);           // [64][128]
    float*  hs = reinterpret_cast<float*>(sm_raw + 65536);    // [64][128]

    int tid = threadIdx.x;
    int lane = tid & 31;
    int warp = tid >> 5;

    // stage Wp (coalesced)
    {
        const float2* src = g_Wp;
        #pragma unroll
        for (int i = 0; i < 32; i++)                  // 8192 / 256
            Wp[tid + i * 256] = src[tid + i * 256];
    }

    // stage hs (coalesced float4)
    int row0 = blockIdx.x * RT;
    for (int idx = tid; idx < RT * 32; idx += 256) {
        int r = idx >> 5;
        int c4 = idx & 31;
        int row = row0 + r;
        float4 h = make_float4(0.f, 0.f, 0.f, 0.f);
        if (row < n)
            h = *reinterpret_cast<const float4*>(&g_h[(size_t)row * C + c4 * 4]);
        *reinterpret_cast<float4*>(&hs[r * C + c4 * 4]) = h;
    }
    __syncthreads();

    unsigned long long acc[8][4];
    #pragma unroll
    for (int r = 0; r < 8; r++)
        #pragma unroll
        for (int j = 0; j < 4; j++) acc[r][j] = 0ULL;

    const unsigned long long* WpU =
        reinterpret_cast<const unsigned long long*>(Wp);

    for (int kp = 0; kp < 64; kp += 2) {
        // W pair-values for cols lane+{0,32,64,96}, at kp and kp+1.
        unsigned long long wA0 = WpU[kp * 128 + lane];
        unsigned long long wA1 = WpU[kp * 128 + lane + 32];
        unsigned long long wA2 = WpU[kp * 128 + lane + 64];
        unsigned long long wA3 = WpU[kp * 128 + lane + 96];
        unsigned long long wB0 = WpU[(kp + 1) * 128 + lane];
        unsigned long long wB1 = WpU[(kp + 1) * 128 + lane + 32];
        unsigned long long wB2 = WpU[(kp + 1) * 128 + lane + 64];
        unsigned long long wB3 = WpU[(kp + 1) * 128 + lane + 96];
        #pragma unroll
        for (int r = 0; r < 8; r++) {
            // h-pairs for kp (hp.x) and kp+1 (hp.y) — broadcast LDS.128
            ulonglong2 hp = *reinterpret_cast<const ulonglong2*>(
                &hs[(warp * 8 + r) * C + kp * 2]);
            FMA2(acc[r][0], hp.x, wA0); FMA2(acc[r][0], hp.y, wB0);
            FMA2(acc[r][1], hp.x, wA1); FMA2(acc[r][1], hp.y, wB1);
            FMA2(acc[r][2], hp.x, wA2); FMA2(acc[r][2], hp.y, wB2);
            FMA2(acc[r][3], hp.x, wA3); FMA2(acc[r][3], hp.y, wB3);
        }
    }

    #pragma unroll
    for (int r = 0; r < 8; r++) {
        int row = row0 + warp * 8 + r;
        if (row >= n) continue;
        float* orow = &out[(size_t)row * C];
        orow[lane]      = pairsum(acc[r][0]);
        orow[lane + 32] = pairsum(acc[r][1]);
        orow[lane + 64] = pairsum(acc[r][2]);
        orow[lane + 96] = pairsum(acc[r][3]);
    }
}

// ---------------------------------------------------------------------------
// kernel_launch
// ---------------------------------------------------------------------------
extern "C" void kernel_launch(void* const* d_in, const int* in_sizes, int n_in,
                              void* d_out, int out_size) {
    const float* x  = (const float*)d_in[0];
    const int*   ei = (const int*)d_in[1];      // int32 (JAX x64 disabled)
    const float* W  = (const float*)d_in[2];
    float* out = (float*)d_out;

    int n = in_sizes[0] / C;        // 100000
    int E = in_sizes[1] / 2;        // 1600000

    const int T = 256;

    init_kernel<<<(n + T - 1) / T, T>>>(W, n);
    deg_kernel<<<(E + T - 1) / T, T>>>(ei, E);
    xs_kernel<<<(n * 32 + T - 1) / T, T>>>(x, n);
    alloc_kernel<<<(n + 255) / 256, 256>>>(n);
    fill_kernel<<<(E + T - 1) / T, T>>>(ei, E);
    agg_kernel<<<(n * 32 + T - 1) / T, T>>>(n);
    {
        int smem = 65536 + RT * C * (int)sizeof(float);   // 96 KB
        cudaFuncSetAttribute(gemm_kernel,
                             cudaFuncAttributeMaxDynamicSharedMemorySize, smem);
        int blocks = (n + RT - 1) / RT;
        gemm_kernel<<<blocks, T, smem>>>(out, n);
    }
}

// round 15
// speedup vs baseline: 1.5959x; 1.0679x over previous
#include <cuda_runtime.h>
#include <cuda_fp16.h>
#include <cstdint>

// GCNConv pipeline — CSR-gather formulation with fp16-staged gather operand.
// Round-15 submission: third attempt at measuring the fp16-gather kernel
// (rounds 13/14 died at broker container acquisition, before compilation).
//
// Pipeline: K0 init+Wprep -> K1 deg -> K2 xs(fp16) -> K3 alloc -> K4 fill
//           -> K5 agg (fp16 gather, fp32 accumulate, exact fp32 self term)
//           -> K6 f32x2-packed GEMM (frozen at FFMA2 floor since round 12)
//
// Problem sizes (reference: N=100000, E=1600000, C=128)
#define MAXN 100000
#define MAXE 1600000
#define C 128

// Scratch (device globals — allocation-free per harness rules)
__device__ __half g_xsh[(size_t)MAXN * C];   // fp16 xs (gather operand)
__device__ float  g_h[(size_t)MAXN * C];
__device__ int    g_ideg[MAXN];
__device__ int    g_rowstart[MAXN];
__device__ int    g_cur[MAXN];
__device__ int    g_csrcol[MAXE];
__device__ int    g_cursor;
__device__ float2 g_Wp[64 * 128];   // [kp][j] = (W[j][2kp], W[j][2kp+1])

// packed-f32x2 FMA: acc(2xf32) += a(2xf32) * b(2xf32)
#define FMA2(acc, a, b) \
    asm("fma.rn.f32x2 %0, %1, %2, %0;" : "+l"(acc) : "l"(a), "l"(b))

__device__ __forceinline__ float pairsum(unsigned long long v) {
    float lo, hi;
    asm("mov.b64 {%0, %1}, %2;" : "=f"(lo), "=f"(hi) : "l"(v));
    return lo + hi;
}

// ---------------------------------------------------------------------------
// K0: zero degree counters + cursor; pre-swizzle W into k-paired layout.
// ---------------------------------------------------------------------------
__global__ void init_kernel(const float* __restrict__ W, int n) {
    int i = blockIdx.x * blockDim.x + threadIdx.x;
    if (i < n) g_ideg[i] = 0;
    if (i == 0) g_cursor = 0;
    if (i < 64 * 128) {
        int kp = i >> 7;
        int j  = i & 127;
        g_Wp[i] = *reinterpret_cast<const float2*>(&W[j * C + kp * 2]);
    }
}

// ---------------------------------------------------------------------------
// K1: integer degree histogram over destination rows (edge_index[0]).
// ---------------------------------------------------------------------------
__global__ void deg_kernel(const int* __restrict__ ei, int E) {
    int e = blockIdx.x * blockDim.x + threadIdx.x;
    if (e >= E) return;
    atomicAdd(&g_ideg[__ldg(&ei[e])], 1);
}

// ---------------------------------------------------------------------------
// K2: g_xsh = fp16( x * rsqrt(deg+1) ).  4 floats -> 4 halves per thread.
// ---------------------------------------------------------------------------
__global__ void xs_kernel(const float* __restrict__ x, int n) {
    int idx = blockIdx.x * blockDim.x + threadIdx.x;   // n*32 float4 units
    if (idx >= n * 32) return;
    int row = idx >> 5;
    float inv = rsqrtf((float)g_ideg[row] + 1.0f);
    float4 v = *reinterpret_cast<const float4*>(&x[(size_t)idx * 4]);
    __half2 h01 = __floats2half2_rn(v.x * inv, v.y * inv);
    __half2 h23 = __floats2half2_rn(v.z * inv, v.w * inv);
    uint2 packed;
    packed.x = *reinterpret_cast<const unsigned*>(&h01);
    packed.y = *reinterpret_cast<const unsigned*>(&h23);
    *reinterpret_cast<uint2*>(&g_xsh[(size_t)idx * 4]) = packed;
}

// ---------------------------------------------------------------------------
// K3: CSR segment allocation — block-aggregated bump allocation
// (one contended global atomic per 256-row block; shuffle scans inside).
// ---------------------------------------------------------------------------
__global__ void __launch_bounds__(256) alloc_kernel(int n) {
    __shared__ int warp_sums[8];
    __shared__ int block_base;

    int tid = threadIdx.x;
    int r = blockIdx.x * 256 + tid;
    int lane = tid & 31;
    int wid = tid >> 5;

    int d = (r < n) ? g_ideg[r] : 0;

    int v = d;
    #pragma unroll
    for (int o = 1; o < 32; o <<= 1) {
        int t = __shfl_up_sync(0xFFFFFFFFu, v, o);
        if (lane >= o) v += t;
    }
    if (lane == 31) warp_sums[wid] = v;
    __syncthreads();

    if (wid == 0) {
        int s = (lane < 8) ? warp_sums[lane] : 0;
        #pragma unroll
        for (int o = 1; o < 8; o <<= 1) {
            int t = __shfl_up_sync(0xFFFFFFFFu, s, o);
            if (lane >= o) s += t;
        }
        if (lane < 8) warp_sums[lane] = s;
        if (lane == 7) block_base = atomicAdd(&g_cursor, s);
    }
    __syncthreads();

    int excl = v - d + (wid > 0 ? warp_sums[wid - 1] : 0) + block_base;
    if (r < n) {
        g_rowstart[r] = excl;
        g_cur[r] = excl;
    }
}

// ---------------------------------------------------------------------------
// K4: fill CSR column lists.
// ---------------------------------------------------------------------------
__global__ void fill_kernel(const int* __restrict__ ei, int E) {
    int e = blockIdx.x * blockDim.x + threadIdx.x;
    if (e >= E) return;
    int row = __ldg(&ei[e]);
    int col = __ldg(&ei[(size_t)E + e]);
    int slot = atomicAdd(&g_cur[row], 1);
    g_csrcol[slot] = col;
}

// ---------------------------------------------------------------------------
// K5: aggregate:  h[r] = (sum_{c in adj(r)} fp16(xs[c]) + x[r]*inv) * inv
// fp16 gather (halves L2 traffic vs fp32), fp32 accumulate, self term exact.
// One warp per row; lane owns 4 channels = one 8B LDG.64 per neighbor
// (256B coalesced per row). Unroll-4 for MLP. Zero smem -> full occupancy.
// ---------------------------------------------------------------------------
__global__ void __launch_bounds__(256) agg_kernel(const float* __restrict__ x,
                                                  int n) {
    int gtid = blockIdx.x * blockDim.x + threadIdx.x;
    int r = gtid >> 5;
    if (r >= n) return;
    int lane = gtid & 31;

    int start = g_rowstart[r];
    int deg = g_ideg[r];
    int end = start + deg;

    float4 a0 = make_float4(0.f, 0.f, 0.f, 0.f);
    float4 a1 = make_float4(0.f, 0.f, 0.f, 0.f);
    float4 a2 = make_float4(0.f, 0.f, 0.f, 0.f);
    float4 a3 = make_float4(0.f, 0.f, 0.f, 0.f);

    const __half* xsh = g_xsh;

    int i = start;
    for (; i + 3 < end; i += 4) {
        int c0 = __ldg(&g_csrcol[i]);
        int c1 = __ldg(&g_csrcol[i + 1]);
        int c2 = __ldg(&g_csrcol[i + 2]);
        int c3 = __ldg(&g_csrcol[i + 3]);
        uint2 p0 = *reinterpret_cast<const uint2*>(&xsh[(size_t)c0 * C + lane * 4]);
        uint2 p1 = *reinterpret_cast<const uint2*>(&xsh[(size_t)c1 * C + lane * 4]);
        uint2 p2 = *reinterpret_cast<const uint2*>(&xsh[(size_t)c2 * C + lane * 4]);
        uint2 p3 = *reinterpret_cast<const uint2*>(&xsh[(size_t)c3 * C + lane * 4]);
        {
            float2 f01 = __half22float2(*reinterpret_cast<__half2*>(&p0.x));
            float2 f23 = __half22float2(*reinterpret_cast<__half2*>(&p0.y));
            a0.x += f01.x; a0.y += f01.y; a0.z += f23.x; a0.w += f23.y;
        }
        {
            float2 f01 = __half22float2(*reinterpret_cast<__half2*>(&p1.x));
            float2 f23 = __half22float2(*reinterpret_cast<__half2*>(&p1.y));
            a1.x += f01.x; a1.y += f01.y; a1.z += f23.x; a1.w += f23.y;
        }
        {
            float2 f01 = __half22float2(*reinterpret_cast<__half2*>(&p2.x));
            float2 f23 = __half22float2(*reinterpret_cast<__half2*>(&p2.y));
            a2.x += f01.x; a2.y += f01.y; a2.z += f23.x; a2.w += f23.y;
        }
        {
            float2 f01 = __half22float2(*reinterpret_cast<__half2*>(&p3.x));
            float2 f23 = __half22float2(*reinterpret_cast<__half2*>(&p3.y));
            a3.x += f01.x; a3.y += f01.y; a3.z += f23.x; a3.w += f23.y;
        }
    }
    for (; i < end; i++) {
        int c0 = __ldg(&g_csrcol[i]);
        uint2 p0 = *reinterpret_cast<const uint2*>(&xsh[(size_t)c0 * C + lane * 4]);
        float2 f01 = __half22float2(*reinterpret_cast<__half2*>(&p0.x));
        float2 f23 = __half22float2(*reinterpret_cast<__half2*>(&p0.y));
        a0.x += f01.x; a0.y += f01.y; a0.z += f23.x; a0.w += f23.y;
    }

    // exact fp32 self contribution: own = x[r] * inv, then everything * inv
    float inv = rsqrtf((float)deg + 1.0f);
    size_t off = (size_t)r * C + lane * 4;
    float4 own = *reinterpret_cast<const float4*>(&x[off]);
    float4 h;
    h.x = (a0.x + a1.x + a2.x + a3.x + own.x * inv) * inv;
    h.y = (a0.y + a1.y + a2.y + a3.y + own.y * inv) * inv;
    h.z = (a0.z + a1.z + a2.z + a3.z + own.z * inv) * inv;
    h.w = (a0.w + a1.w + a2.w + a3.w + own.w * inv) * inv;
    *reinterpret_cast<float4*>(&g_h[off]) = h;
}

// ---------------------------------------------------------------------------
// K6: f32x2-packed GEMM: out = h @ W^T.
// Thread tile 8 rows x 4 cols, cols strided by 32 (col = lane + 32*jg):
// conflict-free LDS.64 W loads (8B lane stride, 256B/warp); k packed in
// pairs, halves folded at epilogue. smem: Wp 64KB + hs 32KB = 96KB.
// ---------------------------------------------------------------------------
#define RT 64
__global__ void __launch_bounds__(256) gemm_kernel(float* __restrict__ out,
                                                   int n) {
    extern __shared__ char sm_raw[];
    float2* Wp = reinterpret_cast<float2*>(sm_raw);           // [64][128]
    float*  hs = reinterpret_cast<float*>(sm_raw + 65536);    // [64][128]

    int tid = threadIdx.x;
    int lane = tid & 31;
    int warp = tid >> 5;

    // stage Wp (coalesced)
    {
        const float2* src = g_Wp;
        #pragma unroll
        for (int i = 0; i < 32; i++)                  // 8192 / 256
            Wp[tid + i * 256] = src[tid + i * 256];
    }

    // stage hs (coalesced float4)
    int row0 = blockIdx.x * RT;
    for (int idx = tid; idx < RT * 32; idx += 256) {
        int r = idx >> 5;
        int c4 = idx & 31;
        int row = row0 + r;
        float4 h = make_float4(0.f, 0.f, 0.f, 0.f);
        if (row < n)
            h = *reinterpret_cast<const float4*>(&g_h[(size_t)row * C + c4 * 4]);
        *reinterpret_cast<float4*>(&hs[r * C + c4 * 4]) = h;
    }
    __syncthreads();

    unsigned long long acc[8][4];
    #pragma unroll
    for (int r = 0; r < 8; r++)
        #pragma unroll
        for (int j = 0; j < 4; j++) acc[r][j] = 0ULL;

    const unsigned long long* WpU =
        reinterpret_cast<const unsigned long long*>(Wp);

    for (int kp = 0; kp < 64; kp += 2) {
        unsigned long long wA0 = WpU[kp * 128 + lane];
        unsigned long long wA1 = WpU[kp * 128 + lane + 32];
        unsigned long long wA2 = WpU[kp * 128 + lane + 64];
        unsigned long long wA3 = WpU[kp * 128 + lane + 96];
        unsigned long long wB0 = WpU[(kp + 1) * 128 + lane];
        unsigned long long wB1 = WpU[(kp + 1) * 128 + lane + 32];
        unsigned long long wB2 = WpU[(kp + 1) * 128 + lane + 64];
        unsigned long long wB3 = WpU[(kp + 1) * 128 + lane + 96];
        #pragma unroll
        for (int r = 0; r < 8; r++) {
            ulonglong2 hp = *reinterpret_cast<const ulonglong2*>(
                &hs[(warp * 8 + r) * C + kp * 2]);
            FMA2(acc[r][0], hp.x, wA0); FMA2(acc[r][0], hp.y, wB0);
            FMA2(acc[r][1], hp.x, wA1); FMA2(acc[r][1], hp.y, wB1);
            FMA2(acc[r][2], hp.x, wA2); FMA2(acc[r][2], hp.y, wB2);
            FMA2(acc[r][3], hp.x, wA3); FMA2(acc[r][3], hp.y, wB3);
        }
    }

    #pragma unroll
    for (int r = 0; r < 8; r++) {
        int row = row0 + warp * 8 + r;
        if (row >= n) continue;
        float* orow = &out[(size_t)row * C];
        orow[lane]      = pairsum(acc[r][0]);
        orow[lane + 32] = pairsum(acc[r][1]);
        orow[lane + 64] = pairsum(acc[r][2]);
        orow[lane + 96] = pairsum(acc[r][3]);
    }
}

// ---------------------------------------------------------------------------
// kernel_launch
// ---------------------------------------------------------------------------
extern "C" void kernel_launch(void* const* d_in, const int* in_sizes, int n_in,
                              void* d_out, int out_size) {
    const float* x  = (const float*)d_in[0];
    const int*   ei = (const int*)d_in[1];      // int32 (JAX x64 disabled)
    const float* W  = (const float*)d_in[2];
    float* out = (float*)d_out;

    int n = in_sizes[0] / C;        // 100000
    int E = in_sizes[1] / 2;        // 1600000

    const int T = 256;

    init_kernel<<<(n + T - 1) / T, T>>>(W, n);
    deg_kernel<<<(E + T - 1) / T, T>>>(ei, E);
    xs_kernel<<<(n * 32 + T - 1) / T, T>>>(x, n);
    alloc_kernel<<<(n + 255) / 256, 256>>>(n);
    fill_kernel<<<(E + T - 1) / T, T>>>(ei, E);
    agg_kernel<<<(n * 32 + T - 1) / T, T>>>(x, n);
    {
        int smem = 65536 + RT * C * (int)sizeof(float);   // 96 KB
        cudaFuncSetAttribute(gemm_kernel,
                             cudaFuncAttributeMaxDynamicSharedMemorySize, smem);
        int blocks = (n + RT - 1) / RT;
        gemm_kernel<<<blocks, T, smem>>>(out, n);
    }
}